// round 1
// baseline (speedup 1.0000x reference)
#include <cuda_runtime.h>
#include <cuda_bf16.h>

// Problem-fixed maxima (N_ATOMS=200000, N_EDGES=5000000, N_BATCH=32)
#define MAX_ATOMS 200000
#define MAX_BATCH 32

// Scratch: per-atom accumulators.
//   g_src[i]      = {sum fij over edges with src==i (x,y,z), unused}
//   g_dst[3i+0]   = {sum -fij (x,y,z), sum v0}
//   g_dst[3i+1]   = {sum v1, v2, v3, v4}
//   g_dst[3i+2]   = {sum v5, unused, unused, unused}
__device__ float4 g_src[MAX_ATOMS];
__device__ float4 g_dst[MAX_ATOMS * 3];
__device__ float  g_sout[MAX_BATCH * 6];   // batch-level virial sums

// ---------------------------------------------------------------------------
// Kernel 1: zero the output buffer and all scratch.
// ---------------------------------------------------------------------------
__global__ void init_kernel(float* __restrict__ out, int out_size, int n_atoms)
{
    int i = blockIdx.x * blockDim.x + threadIdx.x;
    int stride = gridDim.x * blockDim.x;
    const float4 z = make_float4(0.f, 0.f, 0.f, 0.f);
    for (int j = i; j < out_size; j += stride) out[j] = 0.f;
    for (int j = i; j < n_atoms; j += stride) g_src[j] = z;
    for (int j = i; j < n_atoms * 3; j += stride) g_dst[j] = z;
    if (i < MAX_BATCH * 6) g_sout[i] = 0.f;
}

// ---------------------------------------------------------------------------
// Kernel 2: edge scatter. One thread per edge.
//   - force src accumulation:  +fij          -> g_src[src]   (1x red.v4)
//   - force dst + virial:      {-fij, v0..v5} -> g_dst[dst*3] (2x red.v4 + 1 red)
// ---------------------------------------------------------------------------
__global__ void edge_kernel(const float* __restrict__ rij,
                            const float* __restrict__ fij,
                            const int*   __restrict__ eidx,
                            int n_edges)
{
    int e = blockIdx.x * blockDim.x + threadIdx.x;
    if (e >= n_edges) return;

    int src = eidx[e];
    int dst = eidx[n_edges + e];

    float r0 = __ldg(&rij[3 * e + 0]);
    float r1 = __ldg(&rij[3 * e + 1]);
    float r2 = __ldg(&rij[3 * e + 2]);
    float f0 = __ldg(&fij[3 * e + 0]);
    float f1 = __ldg(&fij[3 * e + 1]);
    float f2 = __ldg(&fij[3 * e + 2]);

    // src gets +fij
    asm volatile("red.global.add.v4.f32 [%0], {%1, %2, %3, %4};"
                 :: "l"(&g_src[src]), "f"(f0), "f"(f1), "f"(f2), "f"(0.0f)
                 : "memory");

    // per-edge virial: diag(r*f), r0*f1, r1*f2, r2*f0
    float v0 = r0 * f0, v1 = r1 * f1, v2 = r2 * f2;
    float v3 = r0 * f1, v4 = r1 * f2, v5 = r2 * f0;

    float4* dp = &g_dst[dst * 3];
    asm volatile("red.global.add.v4.f32 [%0], {%1, %2, %3, %4};"
                 :: "l"(dp), "f"(-f0), "f"(-f1), "f"(-f2), "f"(v0)
                 : "memory");
    asm volatile("red.global.add.v4.f32 [%0], {%1, %2, %3, %4};"
                 :: "l"(dp + 1), "f"(v1), "f"(v2), "f"(v3), "f"(v4)
                 : "memory");
    asm volatile("red.global.add.f32 [%0], %1;"
                 :: "l"((float*)(dp + 2)), "f"(v5)
                 : "memory");
}

// ---------------------------------------------------------------------------
// Kernel 3: per-atom pass.
//   - force[i] = g_src[i].xyz + g_dst[3i].xyz  -> out (plain store)
//   - virial per atom -> shared [32][6] -> g_sout (global red)
//   - andev = aniso @ A^T -> shared [32][6] -> out andev region
//   - dev: iso -> shared [32] (all 3 diag entries equal) -> out dev region
// ---------------------------------------------------------------------------
__global__ void atom_kernel(const float* __restrict__ iso,
                            const float* __restrict__ aniso,
                            const int*   __restrict__ batch,
                            float* __restrict__ out,
                            int n_atoms, int n_batch)
{
    __shared__ float s_vir[MAX_BATCH * 6];
    __shared__ float s_andev[MAX_BATCH * 6];
    __shared__ float s_dev[MAX_BATCH];

    for (int t = threadIdx.x; t < MAX_BATCH * 6; t += blockDim.x) {
        s_vir[t] = 0.f;
        s_andev[t] = 0.f;
    }
    if (threadIdx.x < MAX_BATCH) s_dev[threadIdx.x] = 0.f;
    __syncthreads();

    int i = blockIdx.x * blockDim.x + threadIdx.x;
    if (i < n_atoms) {
        float4 s  = g_src[i];
        float4 d0 = g_dst[3 * i + 0];
        float4 d1 = g_dst[3 * i + 1];
        float4 d2 = g_dst[3 * i + 2];

        // force
        out[1 + 3 * i + 0] = s.x + d0.x;
        out[1 + 3 * i + 1] = s.y + d0.y;
        out[1 + 3 * i + 2] = s.z + d0.z;

        int b = batch[i];

        // virial (per-atom -> per-batch)
        atomicAdd(&s_vir[b * 6 + 0], d0.w);
        atomicAdd(&s_vir[b * 6 + 1], d1.x);
        atomicAdd(&s_vir[b * 6 + 2], d1.y);
        atomicAdd(&s_vir[b * 6 + 3], d1.z);
        atomicAdd(&s_vir[b * 6 + 4], d1.w);
        atomicAdd(&s_vir[b * 6 + 5], d2.x);

        // andev = aniso @ A^T
        float a0 = __ldg(&aniso[5 * i + 0]);
        float a1 = __ldg(&aniso[5 * i + 1]);
        float a2 = __ldg(&aniso[5 * i + 2]);
        float a3 = __ldg(&aniso[5 * i + 3]);
        float a4 = __ldg(&aniso[5 * i + 4]);
        const float is6 = 0.4082482904638631f;   // 1/sqrt(6)
        const float s23 = 0.8164965809277260f;   // sqrt(2)/sqrt(3)
        const float is2 = 0.7071067811865476f;   // 1/sqrt(2)
        atomicAdd(&s_andev[b * 6 + 0], -a2 * is6 - a4 * is2);
        atomicAdd(&s_andev[b * 6 + 1],  a2 * s23);
        atomicAdd(&s_andev[b * 6 + 2], -a2 * is6 + a4 * is2);
        atomicAdd(&s_andev[b * 6 + 3],  a1 * is2);
        atomicAdd(&s_andev[b * 6 + 4],  a3 * is2);
        atomicAdd(&s_andev[b * 6 + 5],  a0 * is2);

        // dev: rows are [x,x,x,0,0,0]; accumulate x once
        atomicAdd(&s_dev[b], __ldg(&iso[i]));
    }
    __syncthreads();

    int andev_off = 1 + 3 * n_atoms + 6 * n_batch;
    int dev_off   = andev_off + 6 * n_batch;

    for (int t = threadIdx.x; t < 6 * n_batch; t += blockDim.x) {
        atomicAdd(&g_sout[t], s_vir[t]);
        atomicAdd(&out[andev_off + t], s_andev[t]);
    }
    for (int t = threadIdx.x; t < n_batch; t += blockDim.x) {
        float v = s_dev[t];
        atomicAdd(&out[dev_off + 6 * t + 0], v);
        atomicAdd(&out[dev_off + 6 * t + 1], v);
        atomicAdd(&out[dev_off + 6 * t + 2], v);
        // entries 3..5 stay zero (set by init)
    }
}

// ---------------------------------------------------------------------------
// Kernel 4: finalize. e_tot and stress_drv = -s_out / volume.
// ---------------------------------------------------------------------------
__global__ void finalize_kernel(const float* __restrict__ energy,
                                const float* __restrict__ volume,
                                float* __restrict__ out,
                                int n_atoms, int n_batch)
{
    int t = threadIdx.x;
    int stress_off = 1 + 3 * n_atoms;
    if (t < 6 * n_batch) {
        int b = t / 6;
        out[stress_off + t] = -g_sout[t] / volume[b];
    }
    if (t == 0) {
        float s = 0.f;
        for (int b = 0; b < n_batch; ++b) s += energy[b];
        out[0] = s;
    }
}

// ---------------------------------------------------------------------------
// Launch
// ---------------------------------------------------------------------------
extern "C" void kernel_launch(void* const* d_in, const int* in_sizes, int n_in,
                              void* d_out, int out_size)
{
    const float* rij    = (const float*)d_in[0];
    const float* fij    = (const float*)d_in[1];
    const float* iso    = (const float*)d_in[2];
    const float* aniso  = (const float*)d_in[3];
    const float* volume = (const float*)d_in[4];
    const float* energy = (const float*)d_in[5];
    const int*   eidx   = (const int*)d_in[6];
    const int*   batch  = (const int*)d_in[7];
    float* out = (float*)d_out;

    int n_edges = in_sizes[6] / 2;   // edge_idx is [2, E]
    int n_atoms = in_sizes[7];       // batch is [N]
    int n_batch = in_sizes[4];       // volume is [B]

    init_kernel<<<1024, 256>>>(out, out_size, n_atoms);
    edge_kernel<<<(n_edges + 255) / 256, 256>>>(rij, fij, eidx, n_edges);
    atom_kernel<<<(n_atoms + 255) / 256, 256>>>(iso, aniso, batch, out, n_atoms, n_batch);
    finalize_kernel<<<1, 256>>>(energy, volume, out, n_atoms, n_batch);
}